// round 14
// baseline (speedup 1.0000x reference)
#include <cuda_runtime.h>
#include <cstddef>
#include <cstdint>
#include <math.h>

// Quant-aware attention, bit-matched to the JAX/XLA reference (rel_err == 0.0).
// SACRED (do not reorder): QK/PV sequential fp32 FMA chains ascending over the
// contraction dim (f32x2 halves are independent IEEE chains); expf; softmax sum
// = halves-first tree within each contiguous 32-block then halves-first tree
// over the 32 block partials; IEEE-correct f32 divisions (Markstein 3-op with
// __frcp_rn seed == div.rn.f32 for normals); rintf; clamp.
// R13/R14: phase 1 retiled to 8q x 4k on 128 compute threads (48 LDS wavefronts
// per 128 FFMA2, was 80; K amplification 8x -> 4x); loader warps (tid>=128)
// own the K prefetch. Phases 2/3 unchanged from R12. Bit-neutral.
// (R14 = identical resubmit of R13 after an infra-only bench failure.)

#define S_LEN 1024
#define HD 64
#define QT 32
#define KT1 128           // phase-1 K tile rows
#define KT3 64            // phase-3 V tile rows
#define SCB 1056          // SC row stride in BYTES (int8 codes)
#define QS_STRIDE 68      // floats
#define KS_STRIDE 68      // floats
#define AS_STRIDE 68      // floats
#define KV1_TILE (KT1*KS_STRIDE)         // floats (8704)
#define KV3_TILE (KT3*KS_STRIDE)         // floats (4352)
#define SC_BYTES (QT*SCB)                // 33792
#define SMEM_BYTES (SC_BYTES + 4*(QT*QS_STRIDE) + 4*(2*KV1_TILE))  // 112128

typedef unsigned long long ull;
typedef unsigned int u32;

__device__ __forceinline__ ull ffma2(ull a, ull b, ull c) {
    ull d;
    asm("fma.rn.f32x2 %0, %1, %2, %3;" : "=l"(d) : "l"(a), "l"(b), "l"(c));
    return d;
}
__device__ __forceinline__ ull pack2(float x, float y) {
    ull r; asm("mov.b64 %0, {%1, %2};" : "=l"(r) : "f"(x), "f"(y)); return r;
}
__device__ __forceinline__ void unpack2(ull v, float& lo, float& hi) {
    asm("mov.b64 {%0, %1}, %2;" : "=f"(lo), "=f"(hi) : "l"(v));
}
__device__ __forceinline__ void cp16(u32 s, const void* g) {
    asm volatile("cp.async.cg.shared.global [%0], [%1], 16;" :: "r"(s), "l"(g));
}
#define CP_COMMIT() asm volatile("cp.async.commit_group;")
#define CP_WAIT1()  asm volatile("cp.async.wait_group 1;")
#define CP_WAIT0()  asm volatile("cp.async.wait_group 0;")

// Correctly-rounded x/s given y = __frcp_rn(s) (bit == div.rn.f32 for normals).
__device__ __forceinline__ float fdiv_fast(float x, float s, float y) {
    float q = __fmul_rn(x, y);
    float r = __fmaf_rn(-s, q, x);
    return __fmaf_rn(r, y, q);
}
__device__ __forceinline__ int q8f(float x, float s, float y) {
    float r = rintf(fdiv_fast(x, s, y));
    r = fminf(fmaxf(r, -128.0f), 127.0f);
    return (int)r;
}
__device__ __forceinline__ u32 bex(u32 w, int b) {   // byte b of word w
    return (w >> (8 * b)) & 0xffu;
}

__global__ __launch_bounds__(256, 2)
void attn_qat_kernel(const float* __restrict__ Q,
                     const float* __restrict__ K,
                     const float* __restrict__ V,
                     const float* __restrict__ qk_s_p,
                     const float* __restrict__ a_s_p,
                     const float* __restrict__ av_s_p,
                     float* __restrict__ O) {
    extern __shared__ float smem[];
    char*  SCc = (char*)smem;                           // [QT][SCB] int8 codes
    float* Qs  = (float*)((char*)smem + SC_BYTES);      // [QT][QS_STRIDE] (phase1)
    float* As  = Qs;                                    // overlay (phase3 staging)
    float* KVs = Qs + QT * QS_STRIDE;                   // phase1: [2][KT1][68]
                                                        // phase3: [2][KT3][68] + tables
    float* PT  = KVs + 2 * KV3_TILE;                    // [QT][256] per-row tables

    const int tid   = threadIdx.x;
    const int lane  = tid & 31;
    const int bh    = blockIdx.y;
    const int qbase = blockIdx.x * QT;

    const float qk_s = *qk_s_p;
    const float a_s  = *a_s_p;
    const float av_s = *av_s_p;
    const float y_qk = __frcp_rn(qk_s);
    const float y_a  = __frcp_rn(a_s);
    const float y_av = __frcp_rn(av_s);

    const float* Qg = Q + ((size_t)bh * S_LEN + qbase) * HD;
    const float* Kg = K + (size_t)bh * S_LEN * HD;
    const float* Vg = V + (size_t)bh * S_LEN * HD;

    const u32 kvs_u32 = (u32)__cvta_generic_to_shared(KVs);

    // ---- prologue: loaders async K tile 0 (128x64); compute threads load Q --
    if (tid >= 128) {
        const int lt = tid - 128;
        #pragma unroll
        for (int it = 0; it < 16; it++) {               // 2048 float4 / 128 thr
            int lin = it * 128 + lt;
            int k  = lin >> 4;
            int dq = lin & 15;
            cp16(kvs_u32 + (u32)((k * KS_STRIDE + dq * 4) * 4), Kg + k * HD + dq * 4);
        }
        CP_COMMIT();
    } else {
        #pragma unroll
        for (int it = 0; it < 4; it++) {                // Q: 512 float4 / 128 thr
            int lin = it * 128 + tid;
            int q  = lin >> 4;
            int dq = lin & 15;
            float4 v = *(const float4*)(Qg + q * HD + dq * 4);
            *(float4*)(Qs + q * QS_STRIDE + dq * 4) = v;
        }
    }

    // ===== Phase 1: S codes = q8((Q K^T)/8), 8q x 4k on 128 compute thr =====
    {
        const bool is_loader = (tid >= 128);
        const int lt = tid & 127;
        const int tk = lt & 31;              // k-lane
        const int q0 = (lt >> 5) * 8;        // warp = one q-group of 8 rows

        for (int kt = 0; kt < S_LEN / KT1; kt++) {      // 8 tiles of 128
            const int cur = kt & 1;
            if (is_loader) {
                if (kt < 7) {                // prefetch next K tile
                    const float* src = Kg + (kt + 1) * KT1 * HD;
                    u32 dst = kvs_u32 + (u32)((1 - cur) * KV1_TILE * 4);
                    #pragma unroll
                    for (int it = 0; it < 16; it++) {
                        int lin = it * 128 + lt;
                        int k  = lin >> 4;
                        int dq = lin & 15;
                        cp16(dst + (u32)((k * KS_STRIDE + dq * 4) * 4), src + k * HD + dq * 4);
                    }
                    CP_COMMIT();
                    CP_WAIT1();              // tile kt landed
                } else {
                    CP_WAIT0();
                }
            }
            __syncthreads();                 // publish K(kt)

            if (!is_loader) {
                const float* Kt = KVs + cur * KV1_TILE;

                ull acc2[4][4];  // 4 q-pairs x 4 k-cols {tk+32j}
                #pragma unroll
                for (int p = 0; p < 4; p++)
                    #pragma unroll
                    for (int j = 0; j < 4; j++) acc2[p][j] = pack2(0.f, 0.f);

                #pragma unroll
                for (int d = 0; d < HD; d += 4) {
                    float4 qv[8], kv[4];
                    #pragma unroll
                    for (int i = 0; i < 8; i++)
                        qv[i] = *(const float4*)(Qs + (q0 + i) * QS_STRIDE + d);
                    #pragma unroll
                    for (int j = 0; j < 4; j++)
                        kv[j] = *(const float4*)(Kt + (tk + 32 * j) * KS_STRIDE + d);

                    #define P1STEP(c) { \
                        ull A0 = pack2(qv[0].c, qv[1].c); \
                        ull A1 = pack2(qv[2].c, qv[3].c); \
                        ull A2 = pack2(qv[4].c, qv[5].c); \
                        ull A3 = pack2(qv[6].c, qv[7].c); \
                        _Pragma("unroll") \
                        for (int j = 0; j < 4; j++) { \
                            ull B = pack2(kv[j].c, kv[j].c); \
                            acc2[0][j] = ffma2(A0, B, acc2[0][j]); \
                            acc2[1][j] = ffma2(A1, B, acc2[1][j]); \
                            acc2[2][j] = ffma2(A2, B, acc2[2][j]); \
                            acc2[3][j] = ffma2(A3, B, acc2[3][j]); \
                        } }
                    P1STEP(x) P1STEP(y) P1STEP(z) P1STEP(w)
                    #undef P1STEP
                }

                #pragma unroll
                for (int p = 0; p < 4; p++)
                    #pragma unroll
                    for (int j = 0; j < 4; j++) {
                        float lo, hi;
                        unpack2(acc2[p][j], lo, hi);
                        int col = kt * KT1 + tk + 32 * j;
                        SCc[(q0 + 2 * p    ) * SCB + col] = (char)q8f(lo * 0.125f, qk_s, y_qk);
                        SCc[(q0 + 2 * p + 1) * SCB + col] = (char)q8f(hi * 0.125f, qk_s, y_qk);
                    }
            }
            __syncthreads();                 // guard K buffer reuse
        }
    }

    // ===== Phase 2: softmax via per-row 256-entry tables =====================
    {
        // overlap: all threads prefetch V tile 0 into slot 0 (region is free)
        #pragma unroll
        for (int it = 0; it < 4; it++) {                // 1024 float4 / 256 thr
            int lin = it * 256 + tid;
            int k  = lin >> 4;
            int dq = lin & 15;
            cp16(kvs_u32 + (u32)((k * KS_STRIDE + dq * 4) * 4), Vg + k * HD + dq * 4);
        }
        CP_COMMIT();

        const int w = tid >> 5;              // 8 warps, rows 4w..4w+3

        #pragma unroll
        for (int r = 0; r < 4; r++) {
            char* row = SCc + (4 * w + r) * SCB;
            const int4* rp = (const int4*)(row + 32 * lane);
            int4 wa = rp[0], wb = rp[1];
            u32 xw[8] = {(u32)wa.x ^ 0x80808080u, (u32)wa.y ^ 0x80808080u,
                         (u32)wa.z ^ 0x80808080u, (u32)wa.w ^ 0x80808080u,
                         (u32)wb.x ^ 0x80808080u, (u32)wb.y ^ 0x80808080u,
                         (u32)wb.z ^ 0x80808080u, (u32)wb.w ^ 0x80808080u};

            // integer row max (== fmaxf over dequants; scale > 0, monotonic)
            u32 mx = xw[0];
            #pragma unroll
            for (int k = 1; k < 8; k++) mx = __vmaxu4(mx, xw[k]);
            mx = __vmaxu4(mx, mx >> 16);
            mx = __vmaxu4(mx, mx >> 8);
            mx &= 0xffu;
            #pragma unroll
            for (int o = 16; o; o >>= 1) {
                u32 t = __shfl_xor_sync(0xffffffffu, mx, o);
                mx = mx > t ? mx : t;
            }
            const int   cm = (int)mx - 128;
            const float xm = __fmul_rn((float)cm, qk_s);   // == dequant of max

            // exp table: lane computes 8 candidates (biased codes 8*lane+j)
            float* tabr = PT + (4 * w + r) * 256;
            float ec[8];
            #pragma unroll
            for (int j = 0; j < 8; j++) {
                int cc = 8 * lane + j - 128;
                float xc = __fmul_rn((float)cc, qk_s);     // == dequant (bitwise)
                float d  = __fadd_rn(xc, -xm);             // == row[t] - m
                ec[j] = expf(d);                           // __nv_expf
            }
            *(float4*)(tabr + 8 * lane)     = make_float4(ec[0], ec[1], ec[2], ec[3]);
            *(float4*)(tabr + 8 * lane + 4) = make_float4(ec[4], ec[5], ec[6], ec[7]);
            __syncwarp();

            // sacred sum: halves-first within contiguous 32-block (gathers)...
            float t16[16];
            #pragma unroll
            for (int i = 0; i < 16; i++) {
                float xa = tabr[bex(xw[i >> 2], i & 3)];
                float xb = tabr[bex(xw[(i + 16) >> 2], (i + 16) & 3)];
                t16[i] = xa + xb;
            }
            #pragma unroll
            for (int h = 8; h >= 1; h >>= 1)
                #pragma unroll
                for (int i = 0; i < 8; i++)
                    if (i < h) t16[i] = t16[i] + t16[i + h];
            float p = t16[0];
            // ...then halves-first over the 32 block partials (xor tree)
            #pragma unroll
            for (int o = 16; o; o >>= 1) p += __shfl_xor_sync(0xffffffffu, p, o);
            const float sum_f = p;
            const float y_sum = __frcp_rn(sum_f);
            __syncwarp();                    // all etab reads done before overwrite

            // prob-value table: pr = e/sum, n = q8(pr), store fl(n*a_s)
            float pv[8];
            #pragma unroll
            for (int j = 0; j < 8; j++) {
                float pr = fdiv_fast(ec[j], sum_f, y_sum);
                int n = q8f(pr, a_s, y_a);
                pv[j] = __fmul_rn((float)n, a_s);          // == dequant (bitwise)
            }
            *(float4*)(tabr + 8 * lane)     = make_float4(pv[0], pv[1], pv[2], pv[3]);
            *(float4*)(tabr + 8 * lane + 4) = make_float4(pv[4], pv[5], pv[6], pv[7]);
        }
    }
    __syncthreads();                                    // publish tables

    // ===== Phase 3: O = fq(A V), 4q x 4d on 128 thr; A staged via ptab ======
    {
        const bool is_loader = (tid >= 128);
        const int lt = tid & 127;
        const int td = lt & 15;
        const int tq = lt >> 4;
        const int d0 = td * 4;
        const int q0 = tq * 4;
        const int srow = tid >> 3;           // staging: row 0..31
        const int sseg = tid & 7;            // staging: 8-code segment

        ull acc[4][2];
        #pragma unroll
        for (int i = 0; i < 4; i++) { acc[i][0] = pack2(0.f, 0.f); acc[i][1] = pack2(0.f, 0.f); }

        for (int vt = 0; vt < S_LEN / KT3; vt++) {      // 16 tiles of 64
            const int cur = vt & 1;

            // stage A slice via prob-value table gather (8 values / thread)
            {
                const uint2 w2 = *(const uint2*)(SCc + srow * SCB + vt * KT3 + sseg * 8);
                const u32 xa = w2.x ^ 0x80808080u;
                const u32 xb = w2.y ^ 0x80808080u;
                const float* tabr = PT + srow * 256;
                float4 f0, f1;
                f0.x = tabr[bex(xa, 0)]; f0.y = tabr[bex(xa, 1)];
                f0.z = tabr[bex(xa, 2)]; f0.w = tabr[bex(xa, 3)];
                f1.x = tabr[bex(xb, 0)]; f1.y = tabr[bex(xb, 1)];
                f1.z = tabr[bex(xb, 2)]; f1.w = tabr[bex(xb, 3)];
                *(float4*)(As + srow * AS_STRIDE + sseg * 8)     = f0;
                *(float4*)(As + srow * AS_STRIDE + sseg * 8 + 4) = f1;
            }

            if (is_loader && vt < 15) {      // prefetch V(vt+1)
                const float* src = Vg + (vt + 1) * KT3 * HD;
                u32 dst = kvs_u32 + (u32)((1 - cur) * KV3_TILE * 4);
                #pragma unroll
                for (int it = 0; it < 8; it++) {
                    int lin = it * 128 + lt;
                    int k  = lin >> 4;
                    int dq = lin & 15;
                    cp16(dst + (u32)((k * KS_STRIDE + dq * 4) * 4), src + k * HD + dq * 4);
                }
                CP_COMMIT();
            }
            if (vt < 15) CP_WAIT1(); else CP_WAIT0();
            __syncthreads();                 // publish V(vt) + As

            if (!is_loader) {
                const float* Vt = KVs + cur * KV3_TILE;
                #pragma unroll 2
                for (int k4 = 0; k4 < KT3 / 4; k4++) {
                    float4 a0 = *(const float4*)(As + (q0 + 0) * AS_STRIDE + k4 * 4);
                    float4 a1 = *(const float4*)(As + (q0 + 1) * AS_STRIDE + k4 * 4);
                    float4 a2 = *(const float4*)(As + (q0 + 2) * AS_STRIDE + k4 * 4);
                    float4 a3 = *(const float4*)(As + (q0 + 3) * AS_STRIDE + k4 * 4);

                    #define P3STEP(c, boff) { \
                        ulonglong2 vv = *(const ulonglong2*)(Vt + (k4 * 4 + boff) * KS_STRIDE + d0); \
                        ull A0 = pack2(a0.c, a0.c), A1 = pack2(a1.c, a1.c); \
                        ull A2 = pack2(a2.c, a2.c), A3 = pack2(a3.c, a3.c); \
                        acc[0][0] = ffma2(A0, vv.x, acc[0][0]); \
                        acc[0][1] = ffma2(A0, vv.y, acc[0][1]); \
                        acc[1][0] = ffma2(A1, vv.x, acc[1][0]); \
                        acc[1][1] = ffma2(A1, vv.y, acc[1][1]); \
                        acc[2][0] = ffma2(A2, vv.x, acc[2][0]); \
                        acc[2][1] = ffma2(A2, vv.y, acc[2][1]); \
                        acc[3][0] = ffma2(A3, vv.x, acc[3][0]); \
                        acc[3][1] = ffma2(A3, vv.y, acc[3][1]); }
                    P3STEP(x, 0) P3STEP(y, 1) P3STEP(z, 2) P3STEP(w, 3)
                    #undef P3STEP
                }
            }
            __syncthreads();                 // guard As rewrite + KV buf reuse
        }

        if (!is_loader) {
            #pragma unroll
            for (int i = 0; i < 4; i++) {
                float v0, v1, v2, v3;
                unpack2(acc[i][0], v0, v1);
                unpack2(acc[i][1], v2, v3);
                float4 res;
                res.x = (float)q8f(v0, av_s, y_av) * av_s;
                res.y = (float)q8f(v1, av_s, y_av) * av_s;
                res.z = (float)q8f(v2, av_s, y_av) * av_s;
                res.w = (float)q8f(v3, av_s, y_av) * av_s;
                float* Og = O + ((size_t)bh * S_LEN + qbase + q0 + i) * HD + d0;
                *(float4*)Og = res;
            }
        }
    }
}

extern "C" void kernel_launch(void* const* d_in, const int* in_sizes, int n_in,
                              void* d_out, int out_size) {
    const float* Q    = (const float*)d_in[0];
    const float* K    = (const float*)d_in[1];
    const float* V    = (const float*)d_in[2];
    const float* qk_s = (const float*)d_in[3];
    const float* a_s  = (const float*)d_in[4];
    const float* av_s = (const float*)d_in[5];
    float* O = (float*)d_out;

    const int BH = in_sizes[0] / (S_LEN * HD);   // 128

    cudaFuncSetAttribute(attn_qat_kernel,
                         cudaFuncAttributeMaxDynamicSharedMemorySize, SMEM_BYTES);

    dim3 grid(S_LEN / QT, BH);
    attn_qat_kernel<<<grid, 256, SMEM_BYTES>>>(Q, K, V, qk_s, a_s, av_s, O);
}

// round 15
// speedup vs baseline: 1.0860x; 1.0860x over previous
#include <cuda_runtime.h>
#include <cstddef>
#include <cstdint>
#include <math.h>

// Quant-aware attention, bit-matched to the JAX/XLA reference (rel_err == 0.0).
// SACRED (do not reorder): QK/PV sequential fp32 FMA chains ascending over the
// contraction dim (f32x2 halves are independent IEEE chains); expf; softmax sum
// = halves-first tree within each contiguous 32-block then halves-first tree
// over the 32 block partials; IEEE-correct f32 divisions (Markstein 3-op with
// __frcp_rn seed == div.rn.f32 for normals); rintf; clamp.
// R15: phase 1 = 8q x 2k thread tile on ALL 256 threads (16 LDS wavefronts per
// 32 FFMA2 per warp; total phase-1 wf -20% vs R12) with all-thread prefetch.
// Phases 2/3 identical to R12 (best known). Bit-neutral.

#define S_LEN 1024
#define HD 64
#define QT 32
#define KT1 128           // phase-1 K tile rows
#define KT3 64            // phase-3 V tile rows
#define SCB 1056          // SC row stride in BYTES (int8 codes)
#define QS_STRIDE 68      // floats
#define KS_STRIDE 68      // floats
#define AS_STRIDE 68      // floats
#define KV1_TILE (KT1*KS_STRIDE)         // floats (8704)
#define KV3_TILE (KT3*KS_STRIDE)         // floats (4352)
#define SC_BYTES (QT*SCB)                // 33792
#define SMEM_BYTES (SC_BYTES + 4*(QT*QS_STRIDE) + 4*(2*KV1_TILE))  // 112128

typedef unsigned long long ull;
typedef unsigned int u32;

__device__ __forceinline__ ull ffma2(ull a, ull b, ull c) {
    ull d;
    asm("fma.rn.f32x2 %0, %1, %2, %3;" : "=l"(d) : "l"(a), "l"(b), "l"(c));
    return d;
}
__device__ __forceinline__ ull pack2(float x, float y) {
    ull r; asm("mov.b64 %0, {%1, %2};" : "=l"(r) : "f"(x), "f"(y)); return r;
}
__device__ __forceinline__ void unpack2(ull v, float& lo, float& hi) {
    asm("mov.b64 {%0, %1}, %2;" : "=f"(lo), "=f"(hi) : "l"(v));
}
__device__ __forceinline__ void cp16(u32 s, const void* g) {
    asm volatile("cp.async.cg.shared.global [%0], [%1], 16;" :: "r"(s), "l"(g));
}
#define CP_COMMIT() asm volatile("cp.async.commit_group;")
#define CP_WAIT1()  asm volatile("cp.async.wait_group 1;")
#define CP_WAIT0()  asm volatile("cp.async.wait_group 0;")

// Correctly-rounded x/s given y = __frcp_rn(s) (bit == div.rn.f32 for normals).
__device__ __forceinline__ float fdiv_fast(float x, float s, float y) {
    float q = __fmul_rn(x, y);
    float r = __fmaf_rn(-s, q, x);
    return __fmaf_rn(r, y, q);
}
__device__ __forceinline__ int q8f(float x, float s, float y) {
    float r = rintf(fdiv_fast(x, s, y));
    r = fminf(fmaxf(r, -128.0f), 127.0f);
    return (int)r;
}
__device__ __forceinline__ u32 bex(u32 w, int b) {   // byte b of word w
    return (w >> (8 * b)) & 0xffu;
}

__global__ __launch_bounds__(256, 2)
void attn_qat_kernel(const float* __restrict__ Q,
                     const float* __restrict__ K,
                     const float* __restrict__ V,
                     const float* __restrict__ qk_s_p,
                     const float* __restrict__ a_s_p,
                     const float* __restrict__ av_s_p,
                     float* __restrict__ O) {
    extern __shared__ float smem[];
    char*  SCc = (char*)smem;                           // [QT][SCB] int8 codes
    float* Qs  = (float*)((char*)smem + SC_BYTES);      // [QT][QS_STRIDE] (phase1)
    float* As  = Qs;                                    // overlay (phase3 staging)
    float* KVs = Qs + QT * QS_STRIDE;                   // phase1: [2][KT1][68]
                                                        // phase3: [2][KT3][68] + tables
    float* PT  = KVs + 2 * KV3_TILE;                    // [QT][256] per-row tables

    const int tid   = threadIdx.x;
    const int lane  = tid & 31;
    const int bh    = blockIdx.y;
    const int qbase = blockIdx.x * QT;

    const float qk_s = *qk_s_p;
    const float a_s  = *a_s_p;
    const float av_s = *av_s_p;
    const float y_qk = __frcp_rn(qk_s);
    const float y_a  = __frcp_rn(a_s);
    const float y_av = __frcp_rn(av_s);

    const float* Qg = Q + ((size_t)bh * S_LEN + qbase) * HD;
    const float* Kg = K + (size_t)bh * S_LEN * HD;
    const float* Vg = V + (size_t)bh * S_LEN * HD;

    const u32 kvs_u32 = (u32)__cvta_generic_to_shared(KVs);

    // ---- prologue: async K tile 0 (128x64) + Q tile ----
    {
        #pragma unroll
        for (int it = 0; it < 8; it++) {                // 2048 float4 / 256 thr
            int lin = it * 256 + tid;
            int k  = lin >> 4;
            int dq = lin & 15;
            cp16(kvs_u32 + (u32)((k * KS_STRIDE + dq * 4) * 4), Kg + k * HD + dq * 4);
        }
        CP_COMMIT();
        #pragma unroll
        for (int it = 0; it < 2; it++) {
            int lin = it * 256 + tid;
            int q  = lin >> 4;
            int dq = lin & 15;
            float4 v = *(const float4*)(Qg + q * HD + dq * 4);
            *(float4*)(Qs + q * QS_STRIDE + dq * 4) = v;
        }
    }

    // ===== Phase 1: S codes = q8((Q K^T)/8), 8q x 2k on ALL 256 threads =====
    {
        const int w  = tid >> 5;
        const int tk = lane;
        const int q0 = (w & 3) * 8;          // q-group of 8 rows
        const int kh = (w >> 2) * 64;        // k-half base (0 or 64)

        for (int kt = 0; kt < S_LEN / KT1; kt++) {      // 8 tiles of 128
            const int cur = kt & 1;
            if (kt < 7) {
                const float* src = Kg + (kt + 1) * KT1 * HD;
                u32 dst = kvs_u32 + (u32)((1 - cur) * KV1_TILE * 4);
                #pragma unroll
                for (int it = 0; it < 8; it++) {
                    int lin = it * 256 + tid;
                    int k  = lin >> 4;
                    int dq = lin & 15;
                    cp16(dst + (u32)((k * KS_STRIDE + dq * 4) * 4), src + k * HD + dq * 4);
                }
                CP_COMMIT();
                CP_WAIT1();
            } else {
                CP_WAIT0();
            }
            __syncthreads();

            const float* Kt = KVs + cur * KV1_TILE;

            ull acc2[4][2];  // 4 q-pairs x 2 k-cols {kh+tk, kh+tk+32}
            #pragma unroll
            for (int p = 0; p < 4; p++)
                #pragma unroll
                for (int j = 0; j < 2; j++) acc2[p][j] = pack2(0.f, 0.f);

            #pragma unroll
            for (int d = 0; d < HD; d += 4) {
                float4 qv[8], kv[2];
                #pragma unroll
                for (int i = 0; i < 8; i++)
                    qv[i] = *(const float4*)(Qs + (q0 + i) * QS_STRIDE + d);
                #pragma unroll
                for (int j = 0; j < 2; j++)
                    kv[j] = *(const float4*)(Kt + (kh + tk + 32 * j) * KS_STRIDE + d);

                #define P1STEP(c) { \
                    ull A0 = pack2(qv[0].c, qv[1].c); \
                    ull A1 = pack2(qv[2].c, qv[3].c); \
                    ull A2 = pack2(qv[4].c, qv[5].c); \
                    ull A3 = pack2(qv[6].c, qv[7].c); \
                    _Pragma("unroll") \
                    for (int j = 0; j < 2; j++) { \
                        ull B = pack2(kv[j].c, kv[j].c); \
                        acc2[0][j] = ffma2(A0, B, acc2[0][j]); \
                        acc2[1][j] = ffma2(A1, B, acc2[1][j]); \
                        acc2[2][j] = ffma2(A2, B, acc2[2][j]); \
                        acc2[3][j] = ffma2(A3, B, acc2[3][j]); \
                    } }
                P1STEP(x) P1STEP(y) P1STEP(z) P1STEP(w)
                #undef P1STEP
            }

            #pragma unroll
            for (int p = 0; p < 4; p++)
                #pragma unroll
                for (int j = 0; j < 2; j++) {
                    float lo, hi;
                    unpack2(acc2[p][j], lo, hi);
                    int col = kt * KT1 + kh + tk + 32 * j;
                    SCc[(q0 + 2 * p    ) * SCB + col] = (char)q8f(lo * 0.125f, qk_s, y_qk);
                    SCc[(q0 + 2 * p + 1) * SCB + col] = (char)q8f(hi * 0.125f, qk_s, y_qk);
                }
            __syncthreads();
        }
    }

    // ===== Phase 2: softmax via per-row 256-entry tables =====================
    {
        // overlap: all threads prefetch V tile 0 into slot 0 (region is free)
        #pragma unroll
        for (int it = 0; it < 4; it++) {                // 1024 float4 / 256 thr
            int lin = it * 256 + tid;
            int k  = lin >> 4;
            int dq = lin & 15;
            cp16(kvs_u32 + (u32)((k * KS_STRIDE + dq * 4) * 4), Vg + k * HD + dq * 4);
        }
        CP_COMMIT();

        const int w = tid >> 5;              // 8 warps, rows 4w..4w+3

        #pragma unroll
        for (int r = 0; r < 4; r++) {
            char* row = SCc + (4 * w + r) * SCB;
            const int4* rp = (const int4*)(row + 32 * lane);
            int4 wa = rp[0], wb = rp[1];
            u32 xw[8] = {(u32)wa.x ^ 0x80808080u, (u32)wa.y ^ 0x80808080u,
                         (u32)wa.z ^ 0x80808080u, (u32)wa.w ^ 0x80808080u,
                         (u32)wb.x ^ 0x80808080u, (u32)wb.y ^ 0x80808080u,
                         (u32)wb.z ^ 0x80808080u, (u32)wb.w ^ 0x80808080u};

            // integer row max (== fmaxf over dequants; scale > 0, monotonic)
            u32 mx = xw[0];
            #pragma unroll
            for (int k = 1; k < 8; k++) mx = __vmaxu4(mx, xw[k]);
            mx = __vmaxu4(mx, mx >> 16);
            mx = __vmaxu4(mx, mx >> 8);
            mx &= 0xffu;
            #pragma unroll
            for (int o = 16; o; o >>= 1) {
                u32 t = __shfl_xor_sync(0xffffffffu, mx, o);
                mx = mx > t ? mx : t;
            }
            const int   cm = (int)mx - 128;
            const float xm = __fmul_rn((float)cm, qk_s);   // == dequant of max

            // exp table: lane computes 8 candidates (biased codes 8*lane+j)
            float* tabr = PT + (4 * w + r) * 256;
            float ec[8];
            #pragma unroll
            for (int j = 0; j < 8; j++) {
                int cc = 8 * lane + j - 128;
                float xc = __fmul_rn((float)cc, qk_s);     // == dequant (bitwise)
                float d  = __fadd_rn(xc, -xm);             // == row[t] - m
                ec[j] = expf(d);                           // __nv_expf
            }
            *(float4*)(tabr + 8 * lane)     = make_float4(ec[0], ec[1], ec[2], ec[3]);
            *(float4*)(tabr + 8 * lane + 4) = make_float4(ec[4], ec[5], ec[6], ec[7]);
            __syncwarp();

            // sacred sum: halves-first within contiguous 32-block (gathers)...
            float t16[16];
            #pragma unroll
            for (int i = 0; i < 16; i++) {
                float xa = tabr[bex(xw[i >> 2], i & 3)];
                float xb = tabr[bex(xw[(i + 16) >> 2], (i + 16) & 3)];
                t16[i] = xa + xb;
            }
            #pragma unroll
            for (int h = 8; h >= 1; h >>= 1)
                #pragma unroll
                for (int i = 0; i < 8; i++)
                    if (i < h) t16[i] = t16[i] + t16[i + h];
            float p = t16[0];
            // ...then halves-first over the 32 block partials (xor tree)
            #pragma unroll
            for (int o = 16; o; o >>= 1) p += __shfl_xor_sync(0xffffffffu, p, o);
            const float sum_f = p;
            const float y_sum = __frcp_rn(sum_f);
            __syncwarp();                    // all etab reads done before overwrite

            // prob-value table: pr = e/sum, n = q8(pr), store fl(n*a_s)
            float pv[8];
            #pragma unroll
            for (int j = 0; j < 8; j++) {
                float pr = fdiv_fast(ec[j], sum_f, y_sum);
                int n = q8f(pr, a_s, y_a);
                pv[j] = __fmul_rn((float)n, a_s);          // == dequant (bitwise)
            }
            *(float4*)(tabr + 8 * lane)     = make_float4(pv[0], pv[1], pv[2], pv[3]);
            *(float4*)(tabr + 8 * lane + 4) = make_float4(pv[4], pv[5], pv[6], pv[7]);
        }
    }
    __syncthreads();                                    // publish tables

    // ===== Phase 3: O = fq(A V), 4q x 4d on 128 thr; A staged via ptab ======
    {
        const bool is_loader = (tid >= 128);
        const int lt = tid & 127;
        const int td = lt & 15;
        const int tq = lt >> 4;
        const int d0 = td * 4;
        const int q0 = tq * 4;
        const int srow = tid >> 3;           // staging: row 0..31
        const int sseg = tid & 7;            // staging: 8-code segment

        ull acc[4][2];
        #pragma unroll
        for (int i = 0; i < 4; i++) { acc[i][0] = pack2(0.f, 0.f); acc[i][1] = pack2(0.f, 0.f); }

        for (int vt = 0; vt < S_LEN / KT3; vt++) {      // 16 tiles of 64
            const int cur = vt & 1;

            // stage A slice via prob-value table gather (8 values / thread)
            {
                const uint2 w2 = *(const uint2*)(SCc + srow * SCB + vt * KT3 + sseg * 8);
                const u32 xa = w2.x ^ 0x80808080u;
                const u32 xb = w2.y ^ 0x80808080u;
                const float* tabr = PT + srow * 256;
                float4 f0, f1;
                f0.x = tabr[bex(xa, 0)]; f0.y = tabr[bex(xa, 1)];
                f0.z = tabr[bex(xa, 2)]; f0.w = tabr[bex(xa, 3)];
                f1.x = tabr[bex(xb, 0)]; f1.y = tabr[bex(xb, 1)];
                f1.z = tabr[bex(xb, 2)]; f1.w = tabr[bex(xb, 3)];
                *(float4*)(As + srow * AS_STRIDE + sseg * 8)     = f0;
                *(float4*)(As + srow * AS_STRIDE + sseg * 8 + 4) = f1;
            }

            if (is_loader && vt < 15) {      // prefetch V(vt+1)
                const float* src = Vg + (vt + 1) * KT3 * HD;
                u32 dst = kvs_u32 + (u32)((1 - cur) * KV3_TILE * 4);
                #pragma unroll
                for (int it = 0; it < 8; it++) {
                    int lin = it * 128 + lt;
                    int k  = lin >> 4;
                    int dq = lin & 15;
                    cp16(dst + (u32)((k * KS_STRIDE + dq * 4) * 4), src + k * HD + dq * 4);
                }
                CP_COMMIT();
            }
            if (vt < 15) CP_WAIT1(); else CP_WAIT0();
            __syncthreads();                 // publish V(vt) + As

            if (!is_loader) {
                const float* Vt = KVs + cur * KV3_TILE;
                #pragma unroll 2
                for (int k4 = 0; k4 < KT3 / 4; k4++) {
                    float4 a0 = *(const float4*)(As + (q0 + 0) * AS_STRIDE + k4 * 4);
                    float4 a1 = *(const float4*)(As + (q0 + 1) * AS_STRIDE + k4 * 4);
                    float4 a2 = *(const float4*)(As + (q0 + 2) * AS_STRIDE + k4 * 4);
                    float4 a3 = *(const float4*)(As + (q0 + 3) * AS_STRIDE + k4 * 4);

                    #define P3STEP(c, boff) { \
                        ulonglong2 vv = *(const ulonglong2*)(Vt + (k4 * 4 + boff) * KS_STRIDE + d0); \
                        ull A0 = pack2(a0.c, a0.c), A1 = pack2(a1.c, a1.c); \
                        ull A2 = pack2(a2.c, a2.c), A3 = pack2(a3.c, a3.c); \
                        acc[0][0] = ffma2(A0, vv.x, acc[0][0]); \
                        acc[0][1] = ffma2(A0, vv.y, acc[0][1]); \
                        acc[1][0] = ffma2(A1, vv.x, acc[1][0]); \
                        acc[1][1] = ffma2(A1, vv.y, acc[1][1]); \
                        acc[2][0] = ffma2(A2, vv.x, acc[2][0]); \
                        acc[2][1] = ffma2(A2, vv.y, acc[2][1]); \
                        acc[3][0] = ffma2(A3, vv.x, acc[3][0]); \
                        acc[3][1] = ffma2(A3, vv.y, acc[3][1]); }
                    P3STEP(x, 0) P3STEP(y, 1) P3STEP(z, 2) P3STEP(w, 3)
                    #undef P3STEP
                }
            }
            __syncthreads();                 // guard As rewrite + KV buf reuse
        }

        if (!is_loader) {
            #pragma unroll
            for (int i = 0; i < 4; i++) {
                float v0, v1, v2, v3;
                unpack2(acc[i][0], v0, v1);
                unpack2(acc[i][1], v2, v3);
                float4 res;
                res.x = (float)q8f(v0, av_s, y_av) * av_s;
                res.y = (float)q8f(v1, av_s, y_av) * av_s;
                res.z = (float)q8f(v2, av_s, y_av) * av_s;
                res.w = (float)q8f(v3, av_s, y_av) * av_s;
                float* Og = O + ((size_t)bh * S_LEN + qbase + q0 + i) * HD + d0;
                *(float4*)Og = res;
            }
        }
    }
}

extern "C" void kernel_launch(void* const* d_in, const int* in_sizes, int n_in,
                              void* d_out, int out_size) {
    const float* Q    = (const float*)d_in[0];
    const float* K    = (const float*)d_in[1];
    const float* V    = (const float*)d_in[2];
    const float* qk_s = (const float*)d_in[3];
    const float* a_s  = (const float*)d_in[4];
    const float* av_s = (const float*)d_in[5];
    float* O = (float*)d_out;

    const int BH = in_sizes[0] / (S_LEN * HD);   // 128

    cudaFuncSetAttribute(attn_qat_kernel,
                         cudaFuncAttributeMaxDynamicSharedMemorySize, SMEM_BYTES);

    dim3 grid(S_LEN / QT, BH);
    attn_qat_kernel<<<grid, 256, SMEM_BYTES>>>(Q, K, V, qk_s, a_s, av_s, O);
}